// round 1
// baseline (speedup 1.0000x reference)
#include <cuda_runtime.h>
#include <math.h>

// ---------------------------------------------------------------------------
// Problem constants
// ---------------------------------------------------------------------------
#define Bb   32
#define Cc   128          // channels == DIM_Z == P
#define Pp   128
#define Nn   (Bb * Pp)    // 4096 rows
#define Kk   510
#define KL   512          // K + L
#define Zz   128          // DIM_Z
#define DS   256
#define HW   4096         // 64*64
#define PROTO_ROW (3 * HW)  // 12288 floats per prototype row
#define EPSV 1e-5f

// 1/sqrt(128)
#define INV_NORM 0.08838834764831845f

// weight threshold: dropped mass <= 510 * 1e-8 ~ 5e-6 absolute on S
#define THRESH 1e-8f

// output layout (flat float32 concat of the 4 outputs)
#define OFF_W   0
#define OFF_L   (Nn * KL)            // 2097152
#define OFF_LP  (2 * Nn * KL)        // 4194304
#define OFF_S   (3 * Nn * KL)        // 6291456

// ---------------------------------------------------------------------------
// Device scratch (static globals — no runtime allocation)
// ---------------------------------------------------------------------------
__device__ __align__(16) float g_lat[Kk * Zz];           // LN'd codebook latents
__device__ int            g_cnt[Nn];                     // nnz per row
__device__ unsigned short g_idx[Nn * Kk];                // compact sprite indices
__device__ float          g_wt [Nn * Kk];                // compact weights

// ---------------------------------------------------------------------------
// Block reductions over 128 threads (4 warps)
// ---------------------------------------------------------------------------
__device__ __forceinline__ float bsum128(float v, float* red, int t) {
    #pragma unroll
    for (int o = 16; o; o >>= 1) v += __shfl_down_sync(0xffffffffu, v, o);
    if ((t & 31) == 0) red[t >> 5] = v;
    __syncthreads();
    float r = red[0] + red[1] + red[2] + red[3];
    __syncthreads();
    return r;
}

__device__ __forceinline__ float bmax128(float v, float* red, int t) {
    #pragma unroll
    for (int o = 16; o; o >>= 1) v = fmaxf(v, __shfl_down_sync(0xffffffffu, v, o));
    if ((t & 31) == 0) red[t >> 5] = v;
    __syncthreads();
    float r = fmaxf(fmaxf(red[0], red[1]), fmaxf(red[2], red[3]));
    __syncthreads();
    return r;
}

// ---------------------------------------------------------------------------
// Kernel 1: lat = LN(latents @ linear_w^T + linear_b)   (510 x 128)
// ---------------------------------------------------------------------------
__global__ void k_lat(const float* __restrict__ latents,
                      const float* __restrict__ lw,
                      const float* __restrict__ lb) {
    int k = blockIdx.x;     // 0..509
    int t = threadIdx.x;    // 0..127
    __shared__ float lv[DS];
    __shared__ float red[4];

    lv[t]       = latents[k * DS + t];
    lv[t + 128] = latents[k * DS + t + 128];
    __syncthreads();

    const float* wrow = lw + t * DS;
    float s = lb[t];
    #pragma unroll 8
    for (int d = 0; d < DS; d++) s += lv[d] * wrow[d];

    float mean = bsum128(s, red, t) * (1.0f / 128.0f);
    float d = s - mean;
    float var = bsum128(d * d, red, t) * (1.0f / 128.0f);
    g_lat[k * Zz + t] = d * rsqrtf(var + EPSV);
}

// ---------------------------------------------------------------------------
// Kernel 2: per-row (n = b*P+p):
//   a = LN(x[b,:,p] @ anchors_w^T + anchors_b)
//   logits[0:510] = (a @ lat^T)/NORM ; logits[510:512] = blank dot / NORM
//   weights = softmax, log_probs = log_softmax (permuted layout)
//   deterministic compaction of weights >= THRESH (k < 510)
// ---------------------------------------------------------------------------
__global__ void k_row(const float* __restrict__ x,
                      const float* __restrict__ blankl,
                      const float* __restrict__ aw,
                      const float* __restrict__ ab,
                      float* __restrict__ out) {
    int n = blockIdx.x;           // 0..4095
    int t = threadIdx.x;          // 0..127
    int b = n >> 7, p = n & 127;

    __shared__ float xv[Cc];
    __shared__ float av[Zz];
    __shared__ float lg[KL];
    __shared__ float red[4];
    __shared__ int   ired[4];

    // load x[b, :, p]
    xv[t] = x[b * (Cc * Pp) + t * Pp + p];
    __syncthreads();

    // a_pre[t] = xv . anchors_w[t,:] + ab[t]
    {
        const float* wrow = aw + t * Cc;
        float s = ab[t];
        #pragma unroll 8
        for (int c = 0; c < Cc; c++) s += xv[c] * wrow[c];
        float mean = bsum128(s, red, t) * (1.0f / 128.0f);
        float d = s - mean;
        float var = bsum128(d * d, red, t) * (1.0f / 128.0f);
        av[t] = d * rsqrtf(var + EPSV);
    }

    // blank dot: x[b,:,p] . blank_latent[p % 2, :]
    float partial = xv[t] * blankl[(p & 1) * Cc + t];
    float dotb = bsum128(partial, red, t);
    float lgb = dotb * INV_NORM;
    __syncthreads();   // av visible

    // logits: each thread handles k = t + 128*j, j = 0..3
    #pragma unroll
    for (int j = 0; j < 4; j++) {
        int k = t + (j << 7);
        float val;
        if (k < Kk) {
            const float4* lr = (const float4*)(g_lat + k * Zz);
            float acc = 0.0f;
            #pragma unroll
            for (int i = 0; i < 32; i++) {
                float4 q = lr[i];
                acc += q.x * av[4 * i] + q.y * av[4 * i + 1]
                     + q.z * av[4 * i + 2] + q.w * av[4 * i + 3];
            }
            val = acc * INV_NORM;
        } else {
            val = lgb;
        }
        lg[k] = val;
    }
    __syncthreads();

    // softmax over 512
    float lmax = -1e30f;
    #pragma unroll
    for (int j = 0; j < 4; j++) lmax = fmaxf(lmax, lg[t + (j << 7)]);
    float mx = bmax128(lmax, red, t);

    float lsum = 0.0f;
    float ev[4];
    #pragma unroll
    for (int j = 0; j < 4; j++) {
        ev[j] = expf(lg[t + (j << 7)] - mx);
        lsum += ev[j];
    }
    float sum = bsum128(lsum, red, t);
    float inv_sum = 1.0f / sum;
    float lse = mx + logf(sum);

    // write weights / logits / log_probs + prepare compaction flags
    float* out_w  = out + OFF_W  + (size_t)n * KL;
    float* out_l  = out + OFF_L  + (size_t)n * KL;
    float* out_lp = out + OFF_LP + (size_t)((p << 5) + b) * KL;

    int   flag[4];
    float wv[4];
    #pragma unroll
    for (int j = 0; j < 4; j++) {
        int k = t + (j << 7);
        float l = lg[k];
        float w = ev[j] * inv_sum;
        out_w[k]  = w;
        out_l[k]  = l;
        out_lp[k] = l - lse;
        wv[j] = w;
        flag[j] = (k < Kk && w >= THRESH) ? 1 : 0;
    }

    // deterministic compaction: exclusive prefix scan over 128 threads
    int local = flag[0] + flag[1] + flag[2] + flag[3];
    int v = local;
    #pragma unroll
    for (int o = 1; o < 32; o <<= 1) {
        int u = __shfl_up_sync(0xffffffffu, v, o);
        if ((t & 31) >= o) v += u;
    }
    if ((t & 31) == 31) ired[t >> 5] = v;
    __syncthreads();
    int woff = 0;
    #pragma unroll
    for (int w = 0; w < 4; w++) if (w < (t >> 5)) woff += ired[w];
    int pos = woff + v - local;   // exclusive prefix

    unsigned short* gidx = g_idx + (size_t)n * Kk;
    float*          gwt  = g_wt  + (size_t)n * Kk;
    #pragma unroll
    for (int j = 0; j < 4; j++) {
        if (flag[j]) {
            gidx[pos] = (unsigned short)(t + (j << 7));
            gwt[pos]  = wv[j];
            pos++;
        }
    }
    if (t == 127) g_cnt[n] = woff + v;
}

// ---------------------------------------------------------------------------
// Kernel 3: sparse S = sum_j w_j * sprite[idx_j]  per (row n, channel ch)
// Output S_out[p, b, ch, h, w]
// ---------------------------------------------------------------------------
__global__ void k_sprite(const float* __restrict__ proto,
                         const float* __restrict__ masks,
                         float* __restrict__ out) {
    int ch = blockIdx.x;          // 0..3
    int n  = blockIdx.y;          // 0..4095
    int t  = threadIdx.x;         // 0..255

    int cnt = g_cnt[n];
    __shared__ unsigned short sidx[Kk];
    __shared__ float          sw[Kk];
    for (int i = t; i < cnt; i += 256) {
        sidx[i] = g_idx[(size_t)n * Kk + i];
        sw[i]   = g_wt [(size_t)n * Kk + i];
    }
    __syncthreads();

    float4 a0 = {0,0,0,0}, a1 = {0,0,0,0}, a2 = {0,0,0,0}, a3 = {0,0,0,0};

    for (int i = 0; i < cnt; i++) {
        int k = sidx[i];
        float w = sw[i];
        const float4* src = (ch < 3)
            ? (const float4*)(proto + (size_t)k * PROTO_ROW + ch * HW)
            : (const float4*)(masks + (size_t)k * HW);
        float4 v0 = src[t];
        float4 v1 = src[t + 256];
        float4 v2 = src[t + 512];
        float4 v3 = src[t + 768];
        a0.x += w * v0.x; a0.y += w * v0.y; a0.z += w * v0.z; a0.w += w * v0.w;
        a1.x += w * v1.x; a1.y += w * v1.y; a1.z += w * v1.z; a1.w += w * v1.w;
        a2.x += w * v2.x; a2.y += w * v2.y; a2.z += w * v2.z; a2.w += w * v2.w;
        a3.x += w * v3.x; a3.y += w * v3.y; a3.z += w * v3.z; a3.w += w * v3.w;
    }

    int b = n >> 7, p = n & 127;
    // S_out index: ((p*B + b)*4 + ch) * HW
    float4* dst = (float4*)(out + OFF_S + (size_t)(((p << 5) + b) * 4 + ch) * HW);
    dst[t]       = a0;
    dst[t + 256] = a1;
    dst[t + 512] = a2;
    dst[t + 768] = a3;
}

// ---------------------------------------------------------------------------
// Launch
// ---------------------------------------------------------------------------
extern "C" void kernel_launch(void* const* d_in, const int* in_sizes, int n_in,
                              void* d_out, int out_size) {
    const float* x       = (const float*)d_in[0];  // (32,128,128)
    const float* latents = (const float*)d_in[1];  // (510,256)
    const float* blankl  = (const float*)d_in[2];  // (2,128)
    const float* lw      = (const float*)d_in[3];  // (128,256)
    const float* lb      = (const float*)d_in[4];  // (128,)
    const float* aw      = (const float*)d_in[5];  // (128,128)
    const float* ab      = (const float*)d_in[6];  // (128,)
    const float* proto   = (const float*)d_in[7];  // (510,3,64,64)
    const float* masks   = (const float*)d_in[8];  // (510,1,64,64)
    float* out = (float*)d_out;

    k_lat<<<Kk, 128>>>(latents, lw, lb);
    k_row<<<Nn, 128>>>(x, blankl, aw, ab, out);
    dim3 g3(4, Nn);
    k_sprite<<<g3, 256>>>(proto, masks, out);
}

// round 8
// speedup vs baseline: 4.7280x; 4.7280x over previous
#include <cuda_runtime.h>
#include <cuda_bf16.h>
#include <math.h>
#include <stdint.h>

// ---------------------------------------------------------------------------
// Problem constants
// ---------------------------------------------------------------------------
#define Bb   32
#define Cc   128
#define Pp   128
#define Nn   (Bb * Pp)    // 4096 rows
#define Kk   510
#define KL   512
#define Zz   128
#define DS   256
#define HW   4096
#define EPSV 1e-5f
#define INV_NORM 0.08838834764831845f

#define KP   1536         // split-K: [Wh | Wh | Wl] x [Sh ; Sl ; Sh]
#define Ntot 16384        // 4*HW

// output layout
#define OFF_W   0
#define OFF_L   (Nn * KL)
#define OFF_LP  (2 * Nn * KL)
#define OFF_S   (3 * Nn * KL)

// GEMM tiling (mma.sync path — generic PTX, works on plain sm_103 target)
#define TM 128
#define TN 128
#define TK 32                 // bf16 elems per k-chunk (64 B per row)
#define NCHUNK (KP / TK)      // 48
#define RP 80                 // smem row pitch bytes (5 x 16B -> conflict-free)
#define TILE_BYTES (128 * RP) // 10240 per operand tile
#define STAGE_BYTES (2 * TILE_BYTES)

// ---------------------------------------------------------------------------
// Device scratch
// ---------------------------------------------------------------------------
__device__ __align__(16) float         g_lat[Kk * Zz];
__device__ __align__(16) __nv_bfloat16 g_wA [Nn * KP];           // 12.6 MB
__device__ __align__(16) __nv_bfloat16 g_spT[(size_t)Ntot * KP]; // 50.3 MB

// ---------------------------------------------------------------------------
// PTX helpers (all sm_80-era: safe for generic compute_103 PTX)
// ---------------------------------------------------------------------------
__device__ __forceinline__ uint32_t smem_u32(const void* p) {
    uint32_t a;
    asm("{ .reg .u64 t; cvta.to.shared.u64 t, %1; cvt.u32.u64 %0, t; }"
        : "=r"(a) : "l"(p));
    return a;
}
#define CP_ASYNC16(dst, src) \
    asm volatile("cp.async.cg.shared.global [%0], [%1], 16;" :: "r"(dst), "l"(src))
#define CP_COMMIT() asm volatile("cp.async.commit_group;" ::: "memory")
#define CP_WAIT0()  asm volatile("cp.async.wait_group 0;" ::: "memory")
#define CP_WAIT1()  asm volatile("cp.async.wait_group 1;" ::: "memory")

#define LDSM4(r0, r1, r2, r3, addr) \
    asm volatile("ldmatrix.sync.aligned.m8n8.x4.shared.b16 {%0,%1,%2,%3}, [%4];" \
        : "=r"(r0), "=r"(r1), "=r"(r2), "=r"(r3) : "r"(addr))

__device__ __forceinline__ void mma16816(float* c, const uint32_t* a,
                                         const uint32_t* b) {
    asm volatile(
        "mma.sync.aligned.m16n8k16.row.col.f32.bf16.bf16.f32 "
        "{%0,%1,%2,%3}, {%4,%5,%6,%7}, {%8,%9}, {%0,%1,%2,%3};"
        : "+f"(c[0]), "+f"(c[1]), "+f"(c[2]), "+f"(c[3])
        : "r"(a[0]), "r"(a[1]), "r"(a[2]), "r"(a[3]), "r"(b[0]), "r"(b[1]));
}

// ---------------------------------------------------------------------------
// Block reductions (128 threads)
// ---------------------------------------------------------------------------
__device__ __forceinline__ float bsum128(float v, float* red, int t) {
    #pragma unroll
    for (int o = 16; o; o >>= 1) v += __shfl_down_sync(0xffffffffu, v, o);
    if ((t & 31) == 0) red[t >> 5] = v;
    __syncthreads();
    float r = red[0] + red[1] + red[2] + red[3];
    __syncthreads();
    return r;
}
__device__ __forceinline__ float bmax128(float v, float* red, int t) {
    #pragma unroll
    for (int o = 16; o; o >>= 1) v = fmaxf(v, __shfl_down_sync(0xffffffffu, v, o));
    if ((t & 31) == 0) red[t >> 5] = v;
    __syncthreads();
    float r = fmaxf(fmaxf(red[0], red[1]), fmaxf(red[2], red[3]));
    __syncthreads();
    return r;
}

// ---------------------------------------------------------------------------
// Kernel 1: lat = LN(latents @ linear_w^T + linear_b), 4 latents per block
// ---------------------------------------------------------------------------
__global__ void k_lat(const float* __restrict__ latents,
                      const float* __restrict__ lw,
                      const float* __restrict__ lb) {
    int k0 = blockIdx.x * 4;
    int t = threadIdx.x;
    __shared__ float lv[4][DS];
    __shared__ float red[4][4];

    #pragma unroll
    for (int r = 0; r < 4; r++) {
        int k = k0 + r;
        float a = 0.f, b2 = 0.f;
        if (k < Kk) { a = latents[k * DS + t]; b2 = latents[k * DS + t + 128]; }
        lv[r][t] = a; lv[r][t + 128] = b2;
    }
    __syncthreads();

    const float* wrow = lw + t * DS;
    float s[4] = {lb[t], lb[t], lb[t], lb[t]};
    #pragma unroll 4
    for (int d = 0; d < DS; d++) {
        float w = wrow[d];
        #pragma unroll
        for (int r = 0; r < 4; r++) s[r] += lv[r][d] * w;
    }

    float v[4];
    #pragma unroll
    for (int r = 0; r < 4; r++) v[r] = s[r];
    #pragma unroll
    for (int o = 16; o; o >>= 1)
        #pragma unroll
        for (int r = 0; r < 4; r++) v[r] += __shfl_down_sync(0xffffffffu, v[r], o);
    if ((t & 31) == 0)
        #pragma unroll
        for (int r = 0; r < 4; r++) red[t >> 5][r] = v[r];
    __syncthreads();
    float d4[4];
    #pragma unroll
    for (int r = 0; r < 4; r++) {
        float m = (red[0][r] + red[1][r] + red[2][r] + red[3][r]) * (1.f / 128.f);
        d4[r] = s[r] - m;
        v[r] = d4[r] * d4[r];
    }
    __syncthreads();
    #pragma unroll
    for (int o = 16; o; o >>= 1)
        #pragma unroll
        for (int r = 0; r < 4; r++) v[r] += __shfl_down_sync(0xffffffffu, v[r], o);
    if ((t & 31) == 0)
        #pragma unroll
        for (int r = 0; r < 4; r++) red[t >> 5][r] = v[r];
    __syncthreads();
    #pragma unroll
    for (int r = 0; r < 4; r++) {
        int k = k0 + r;
        if (k < Kk) {
            float var = (red[0][r] + red[1][r] + red[2][r] + red[3][r]) * (1.f / 128.f);
            g_lat[k * Zz + t] = d4[r] * rsqrtf(var + EPSV);
        }
    }
}

// ---------------------------------------------------------------------------
// Kernel 2: sprite^T bf16 hi/lo, [Ntot, KP] K-major
// ---------------------------------------------------------------------------
__global__ void k_prep(const float* __restrict__ proto,
                       const float* __restrict__ masks) {
    __shared__ float tile[64][65];
    int n0 = blockIdx.x * 64;
    int k0 = blockIdx.y * 64;
    int t = threadIdx.x;

    for (int idx = t; idx < 4096; idx += 256) {
        int kk = idx >> 6, nn = idx & 63;
        int k = k0 + kk, n = n0 + nn;
        int ch = n >> 12, i = n & 4095;
        float s = 0.f;
        if (k < Kk)
            s = (ch < 3) ? proto[(size_t)k * (3 * HW) + ch * HW + i]
                         : masks[(size_t)k * HW + i];
        tile[kk][nn] = s;
    }
    __syncthreads();

    for (int idx = t; idx < 4096; idx += 256) {
        int nn = idx >> 6, kk = idx & 63;
        float s = tile[kk][nn];
        __nv_bfloat16 hi = __float2bfloat16(s);
        __nv_bfloat16 lo = __float2bfloat16(s - __bfloat162float(hi));
        size_t base = (size_t)(n0 + nn) * KP + k0 + kk;
        g_spT[base]        = hi;
        g_spT[base + 512]  = lo;
        g_spT[base + 1024] = hi;
    }
}

// ---------------------------------------------------------------------------
// Kernel 3: per-row logits / softmax / log_softmax; writes split-bf16 weights
// into g_wA rows ordered m = p*32 + b.
// ---------------------------------------------------------------------------
__global__ void k_row(const float* __restrict__ x,
                      const float* __restrict__ blankl,
                      const float* __restrict__ aw,
                      const float* __restrict__ ab,
                      float* __restrict__ out) {
    int n = blockIdx.x;
    int t = threadIdx.x;
    int b = n >> 7, p = n & 127;

    __shared__ float xv[Cc];
    __shared__ float av[Zz];
    __shared__ float lg[KL];
    __shared__ float red[4];

    xv[t] = x[b * (Cc * Pp) + t * Pp + p];
    __syncthreads();

    {
        const float* wrow = aw + t * Cc;
        float s = ab[t];
        #pragma unroll 8
        for (int c = 0; c < Cc; c++) s += xv[c] * wrow[c];
        float mean = bsum128(s, red, t) * (1.0f / 128.0f);
        float d = s - mean;
        float var = bsum128(d * d, red, t) * (1.0f / 128.0f);
        av[t] = d * rsqrtf(var + EPSV);
    }

    float partial = xv[t] * blankl[(p & 1) * Cc + t];
    float lgb = bsum128(partial, red, t) * INV_NORM;
    __syncthreads();

    #pragma unroll
    for (int j = 0; j < 4; j++) {
        int k = t + (j << 7);
        float val;
        if (k < Kk) {
            const float4* lr = (const float4*)(g_lat + k * Zz);
            float acc = 0.0f;
            #pragma unroll
            for (int i = 0; i < 32; i++) {
                float4 q = lr[i];
                acc += q.x * av[4 * i] + q.y * av[4 * i + 1]
                     + q.z * av[4 * i + 2] + q.w * av[4 * i + 3];
            }
            val = acc * INV_NORM;
        } else {
            val = lgb;
        }
        lg[k] = val;
    }
    __syncthreads();

    float lmax = -1e30f;
    #pragma unroll
    for (int j = 0; j < 4; j++) lmax = fmaxf(lmax, lg[t + (j << 7)]);
    float mx = bmax128(lmax, red, t);

    float lsum = 0.0f, ev[4];
    #pragma unroll
    for (int j = 0; j < 4; j++) {
        ev[j] = expf(lg[t + (j << 7)] - mx);
        lsum += ev[j];
    }
    float sum = bsum128(lsum, red, t);
    float inv_sum = 1.0f / sum;
    float lse = mx + logf(sum);

    int m = (p << 5) + b;
    float* out_w  = out + OFF_W  + (size_t)n * KL;
    float* out_l  = out + OFF_L  + (size_t)n * KL;
    float* out_lp = out + OFF_LP + (size_t)m * KL;
    __nv_bfloat16* wa = g_wA + (size_t)m * KP;

    #pragma unroll
    for (int j = 0; j < 4; j++) {
        int k = t + (j << 7);
        float l = lg[k];
        float w = ev[j] * inv_sum;
        out_w[k]  = w;
        out_l[k]  = l;
        out_lp[k] = l - lse;
        __nv_bfloat16 hi = __float2bfloat16(w);
        __nv_bfloat16 lo = __float2bfloat16(w - __bfloat162float(hi));
        wa[k]        = hi;
        wa[k + 512]  = hi;
        wa[k + 1024] = lo;
    }
}

// ---------------------------------------------------------------------------
// Kernel 4: mma.sync bf16 GEMM  C[4096,16384] = A[4096,1536] @ B[16384,1536]^T
// CTA 128x128x32, 8 warps (4M x 2N), warp tile 32x64, double-buffered cp.async
// ---------------------------------------------------------------------------
__global__ void __launch_bounds__(256) k_gemm(float* __restrict__ outS) {
    __shared__ __align__(128) char sm[2 * STAGE_BYTES];   // [stage][A|B]

    int t = threadIdx.x;
    int lane = t & 31;
    int wid = t >> 5;
    int warp_m = wid & 3;          // 0..3 -> 32-row slice
    int warp_n = wid >> 2;         // 0..1 -> 64-col slice
    int n0 = blockIdx.x * TN;
    int m0 = blockIdx.y * TM;

    uint32_t smb = smem_u32(sm);

    // cp.async chunk mapping: q in [0,512): row = q>>2, 16B-chunk col = q&3
    int qr0 = t >> 2, qc0 = t & 3;
    int qr1 = (t + 256) >> 2, qc1 = t & 3;   // (t+256)&3 == t&3

    const char* gA = (const char*)g_wA  + (size_t)(m0 + qr0) * (KP * 2);
    const char* gA1 = (const char*)g_wA + (size_t)(m0 + qr1) * (KP * 2);
    const char* gB = (const char*)g_spT + (size_t)(n0 + qr0) * (KP * 2);
    const char* gB1 = (const char*)g_spT + (size_t)(n0 + qr1) * (KP * 2);

    uint32_t sA0 = smb + qr0 * RP + qc0 * 16;
    uint32_t sA1 = smb + qr1 * RP + qc1 * 16;
    uint32_t sB0 = sA0 + TILE_BYTES;
    uint32_t sB1 = sA1 + TILE_BYTES;

    // ldmatrix per-lane base addresses
    uint32_t lmA = smb + (warp_m * 32 + (lane & 15)) * RP + (lane >> 4) * 16;
    uint32_t lmB = smb + TILE_BYTES
                 + (warp_n * 64 + (lane & 7) + ((lane >> 4) & 1) * 8) * RP
                 + ((lane >> 3) & 1) * 16;

    float acc[2][8][4];
    #pragma unroll
    for (int mt = 0; mt < 2; mt++)
        #pragma unroll
        for (int nt = 0; nt < 8; nt++)
            #pragma unroll
            for (int q = 0; q < 4; q++) acc[mt][nt][q] = 0.f;

    // prefetch chunk 0 into stage 0
    {
        int cb = 0;
        CP_ASYNC16(sA0, gA  + cb + qc0 * 16);
        CP_ASYNC16(sA1, gA1 + cb + qc1 * 16);
        CP_ASYNC16(sB0, gB  + cb + qc0 * 16);
        CP_ASYNC16(sB1, gB1 + cb + qc1 * 16);
        CP_COMMIT();
    }

    for (int c = 0; c < NCHUNK; c++) {
        int st = c & 1;
        if (c + 1 < NCHUNK) {
            int cb = (c + 1) * 64;       // byte offset along K
            uint32_t so = ((c + 1) & 1) * STAGE_BYTES;
            CP_ASYNC16(sA0 + so, gA  + cb + qc0 * 16);
            CP_ASYNC16(sA1 + so, gA1 + cb + qc1 * 16);
            CP_ASYNC16(sB0 + so, gB  + cb + qc0 * 16);
            CP_ASYNC16(sB1 + so, gB1 + cb + qc1 * 16);
            CP_COMMIT();
            CP_WAIT1();
        } else {
            CP_WAIT0();
        }
        __syncthreads();

        uint32_t aoff = lmA + st * STAGE_BYTES;
        uint32_t boff = lmB + st * STAGE_BYTES;
        #pragma unroll
        for (int kt = 0; kt < 2; kt++) {
            uint32_t a[2][4];
            #pragma unroll
            for (int mt = 0; mt < 2; mt++)
                LDSM4(a[mt][0], a[mt][1], a[mt][2], a[mt][3],
                      aoff + mt * (16 * RP) + kt * 32);
            uint32_t bfr[8][2];
            #pragma unroll
            for (int pgrp = 0; pgrp < 4; pgrp++)
                LDSM4(bfr[2 * pgrp][0], bfr[2 * pgrp][1],
                      bfr[2 * pgrp + 1][0], bfr[2 * pgrp + 1][1],
                      boff + pgrp * (16 * RP) + kt * 32);
            #pragma unroll
            for (int mt = 0; mt < 2; mt++)
                #pragma unroll
                for (int nt = 0; nt < 8; nt++)
                    mma16816(acc[mt][nt], a[mt], bfr[nt]);
        }
        __syncthreads();
    }

    // epilogue: direct stores
    int rbase = m0 + warp_m * 32 + (lane >> 2);
    int cbase = n0 + warp_n * 64 + (lane & 3) * 2;
    #pragma unroll
    for (int mt = 0; mt < 2; mt++) {
        #pragma unroll
        for (int nt = 0; nt < 8; nt++) {
            int r = rbase + mt * 16;
            int cc = cbase + nt * 8;
            float2 v0 = make_float2(acc[mt][nt][0], acc[mt][nt][1]);
            float2 v1 = make_float2(acc[mt][nt][2], acc[mt][nt][3]);
            *(float2*)(outS + (size_t)r * Ntot + cc) = v0;
            *(float2*)(outS + (size_t)(r + 8) * Ntot + cc) = v1;
        }
    }
}

// ---------------------------------------------------------------------------
// Launch
// ---------------------------------------------------------------------------
extern "C" void kernel_launch(void* const* d_in, const int* in_sizes, int n_in,
                              void* d_out, int out_size) {
    const float* x       = (const float*)d_in[0];
    const float* latents = (const float*)d_in[1];
    const float* blankl  = (const float*)d_in[2];
    const float* lw      = (const float*)d_in[3];
    const float* lb      = (const float*)d_in[4];
    const float* aw      = (const float*)d_in[5];
    const float* ab      = (const float*)d_in[6];
    const float* proto   = (const float*)d_in[7];
    const float* masks   = (const float*)d_in[8];
    float* out = (float*)d_out;

    k_lat<<<(Kk + 3) / 4, 128>>>(latents, lw, lb);
    dim3 gp(Ntot / 64, KL / 64);
    k_prep<<<gp, 256>>>(proto, masks);
    k_row<<<Nn, 128>>>(x, blankl, aw, ab, out);
    dim3 gg(Ntot / TN, Nn / TM);
    k_gemm<<<gg, 256>>>(out + OFF_S);
}

// round 9
// speedup vs baseline: 13.3929x; 2.8327x over previous
#include <cuda_runtime.h>
#include <cuda_fp16.h>
#include <math.h>
#include <stdint.h>

// ---------------------------------------------------------------------------
// Problem constants
// ---------------------------------------------------------------------------
#define Bb   32
#define Cc   128
#define Pp   128
#define Nn   (Bb * Pp)    // 4096 rows
#define Kk   510
#define KL   512
#define Zz   128
#define DS   256
#define HW   4096
#define EPSV 1e-5f
#define INV_NORM 0.08838834764831845f

#define KP   512          // single-term fp16 GEMM
#define Ntot 16384        // 4*HW

// output layout
#define OFF_W   0
#define OFF_L   (Nn * KL)
#define OFF_LP  (2 * Nn * KL)
#define OFF_S   (3 * Nn * KL)

// GEMM tiling (generic-PTX mma.sync path)
#define TM 128
#define TN 128
#define TK 32                 // fp16 elems per k-chunk (64 B per row)
#define NCHUNK (KP / TK)      // 16
#define RP 80                 // smem row pitch bytes (64B data + 16 pad)
#define TILE_BYTES (128 * RP) // 10240 per operand tile
#define STAGE_BYTES (2 * TILE_BYTES)

// ---------------------------------------------------------------------------
// Device scratch (zero-initialized at load; rows k>=510 of g_spT stay zero)
// ---------------------------------------------------------------------------
__device__ __align__(16) float  g_lat[Kk * Zz];
__device__ __align__(16) __half g_wA [Nn * KP];            // 4.2 MB
__device__ __align__(16) __half g_spT[(size_t)Ntot * KP];  // 16.8 MB

// ---------------------------------------------------------------------------
// PTX helpers (sm_80-era; valid for plain compute_103 target)
// ---------------------------------------------------------------------------
__device__ __forceinline__ uint32_t smem_u32(const void* p) {
    uint32_t a;
    asm("{ .reg .u64 t; cvta.to.shared.u64 t, %1; cvt.u32.u64 %0, t; }"
        : "=r"(a) : "l"(p));
    return a;
}
#define CP_ASYNC16(dst, src) \
    asm volatile("cp.async.cg.shared.global [%0], [%1], 16;" :: "r"(dst), "l"(src))
#define CP_COMMIT() asm volatile("cp.async.commit_group;" ::: "memory")
#define CP_WAIT0()  asm volatile("cp.async.wait_group 0;" ::: "memory")
#define CP_WAIT1()  asm volatile("cp.async.wait_group 1;" ::: "memory")

#define LDSM4(r0, r1, r2, r3, addr) \
    asm volatile("ldmatrix.sync.aligned.m8n8.x4.shared.b16 {%0,%1,%2,%3}, [%4];" \
        : "=r"(r0), "=r"(r1), "=r"(r2), "=r"(r3) : "r"(addr))

__device__ __forceinline__ void mma16816(float* c, const uint32_t* a,
                                         const uint32_t* b) {
    asm volatile(
        "mma.sync.aligned.m16n8k16.row.col.f32.f16.f16.f32 "
        "{%0,%1,%2,%3}, {%4,%5,%6,%7}, {%8,%9}, {%0,%1,%2,%3};"
        : "+f"(c[0]), "+f"(c[1]), "+f"(c[2]), "+f"(c[3])
        : "r"(a[0]), "r"(a[1]), "r"(a[2]), "r"(a[3]), "r"(b[0]), "r"(b[1]));
}

// ---------------------------------------------------------------------------
// 4-row block reductions over 128 threads
// ---------------------------------------------------------------------------
__device__ __forceinline__ void redsum4(float v[4], float red[4][4], int t) {
    #pragma unroll
    for (int o = 16; o; o >>= 1)
        #pragma unroll
        for (int r = 0; r < 4; r++) v[r] += __shfl_down_sync(0xffffffffu, v[r], o);
    if ((t & 31) == 0)
        #pragma unroll
        for (int r = 0; r < 4; r++) red[t >> 5][r] = v[r];
    __syncthreads();
    #pragma unroll
    for (int r = 0; r < 4; r++)
        v[r] = red[0][r] + red[1][r] + red[2][r] + red[3][r];
    __syncthreads();
}
__device__ __forceinline__ void redmax4(float v[4], float red[4][4], int t) {
    #pragma unroll
    for (int o = 16; o; o >>= 1)
        #pragma unroll
        for (int r = 0; r < 4; r++)
            v[r] = fmaxf(v[r], __shfl_down_sync(0xffffffffu, v[r], o));
    if ((t & 31) == 0)
        #pragma unroll
        for (int r = 0; r < 4; r++) red[t >> 5][r] = v[r];
    __syncthreads();
    #pragma unroll
    for (int r = 0; r < 4; r++)
        v[r] = fmaxf(fmaxf(red[0][r], red[1][r]), fmaxf(red[2][r], red[3][r]));
    __syncthreads();
}

// ---------------------------------------------------------------------------
// Kernel 1: lat = LN(latents @ linear_w^T + linear_b), 4 latents per block
// ---------------------------------------------------------------------------
__global__ void k_lat(const float* __restrict__ latents,
                      const float* __restrict__ lw,
                      const float* __restrict__ lb) {
    int k0 = blockIdx.x * 4;
    int t = threadIdx.x;
    __shared__ float lv[4][DS];
    __shared__ float red[4][4];

    #pragma unroll
    for (int r = 0; r < 4; r++) {
        int k = k0 + r;
        float a = 0.f, b2 = 0.f;
        if (k < Kk) { a = latents[k * DS + t]; b2 = latents[k * DS + t + 128]; }
        lv[r][t] = a; lv[r][t + 128] = b2;
    }
    __syncthreads();

    const float* wrow = lw + t * DS;
    float s[4] = {lb[t], lb[t], lb[t], lb[t]};
    #pragma unroll 4
    for (int d = 0; d < DS; d++) {
        float w = wrow[d];
        #pragma unroll
        for (int r = 0; r < 4; r++) s[r] += lv[r][d] * w;
    }

    float v[4];
    #pragma unroll
    for (int r = 0; r < 4; r++) v[r] = s[r];
    redsum4(v, red, t);
    float d4[4];
    #pragma unroll
    for (int r = 0; r < 4; r++) {
        d4[r] = s[r] - v[r] * (1.f / 128.f);
        v[r] = d4[r] * d4[r];
    }
    redsum4(v, red, t);
    #pragma unroll
    for (int r = 0; r < 4; r++) {
        int k = k0 + r;
        if (k < Kk)
            g_lat[k * Zz + t] = d4[r] * rsqrtf(v[r] * (1.f / 128.f) + EPSV);
    }
}

// ---------------------------------------------------------------------------
// Kernel 2: sprite^T fp16, [Ntot, KP] K-major (rows k>=510 remain zero)
// ---------------------------------------------------------------------------
__global__ void k_prep(const float* __restrict__ proto,
                       const float* __restrict__ masks) {
    __shared__ float tile[64][65];
    int n0 = blockIdx.x * 64;
    int k0 = blockIdx.y * 64;
    int t = threadIdx.x;

    for (int idx = t; idx < 4096; idx += 256) {
        int kk = idx >> 6, nn = idx & 63;
        int k = k0 + kk, n = n0 + nn;
        int ch = n >> 12, i = n & 4095;
        float s = 0.f;
        if (k < Kk)
            s = (ch < 3) ? proto[(size_t)k * (3 * HW) + ch * HW + i]
                         : masks[(size_t)k * HW + i];
        tile[kk][nn] = s;
    }
    __syncthreads();

    for (int idx = t; idx < 4096; idx += 256) {
        int nn = idx >> 6, kk = idx & 63;
        if (k0 + kk < Kk)
            g_spT[(size_t)(n0 + nn) * KP + k0 + kk] = __float2half(tile[kk][nn]);
    }
}

// ---------------------------------------------------------------------------
// Kernel 3: 4 rows per block (same p, 4 consecutive b): logits / softmax /
// log_softmax outputs + fp16 weight rows into g_wA (m = p*32 + b)
// ---------------------------------------------------------------------------
__global__ void k_row(const float* __restrict__ x,
                      const float* __restrict__ blankl,
                      const float* __restrict__ aw,
                      const float* __restrict__ ab,
                      float* __restrict__ out) {
    int bi = blockIdx.x;          // 0..1023
    int p  = bi & 127;
    int bq = bi >> 7;             // 0..7 -> b = bq*4 + r
    int t  = threadIdx.x;

    __shared__ float xv[4][Cc];
    __shared__ float av[4][Zz];
    __shared__ float lg[4][KL];
    __shared__ float red[4][4];

    #pragma unroll
    for (int r = 0; r < 4; r++)
        xv[r][t] = x[(size_t)(bq * 4 + r) * (Cc * Pp) + t * Pp + p];
    __syncthreads();

    // anchors linear + LN (4 rows)
    {
        const float* wrow = aw + t * Cc;
        float s[4] = {ab[t], ab[t], ab[t], ab[t]};
        #pragma unroll 4
        for (int c = 0; c < Cc; c++) {
            float w = wrow[c];
            #pragma unroll
            for (int r = 0; r < 4; r++) s[r] += xv[r][c] * w;
        }
        float v[4];
        #pragma unroll
        for (int r = 0; r < 4; r++) v[r] = s[r];
        redsum4(v, red, t);
        float d4[4];
        #pragma unroll
        for (int r = 0; r < 4; r++) {
            d4[r] = s[r] - v[r] * (1.f / 128.f);
            v[r] = d4[r] * d4[r];
        }
        redsum4(v, red, t);
        #pragma unroll
        for (int r = 0; r < 4; r++)
            av[r][t] = d4[r] * rsqrtf(v[r] * (1.f / 128.f) + EPSV);
    }

    // blank dots (4 rows)
    float lgb[4];
    {
        float bl = blankl[(p & 1) * Cc + t];
        float v[4];
        #pragma unroll
        for (int r = 0; r < 4; r++) v[r] = xv[r][t] * bl;
        redsum4(v, red, t);
        #pragma unroll
        for (int r = 0; r < 4; r++) lgb[r] = v[r] * INV_NORM;
    }
    __syncthreads();   // av visible

    // logits: thread handles k = t + 128*j for all 4 rows
    #pragma unroll
    for (int j = 0; j < 4; j++) {
        int k = t + (j << 7);
        if (k < Kk) {
            const float4* lr = (const float4*)(g_lat + k * Zz);
            float acc[4] = {0.f, 0.f, 0.f, 0.f};
            #pragma unroll 8
            for (int i = 0; i < 32; i++) {
                float4 q = lr[i];
                #pragma unroll
                for (int r = 0; r < 4; r++)
                    acc[r] += q.x * av[r][4 * i]     + q.y * av[r][4 * i + 1]
                            + q.z * av[r][4 * i + 2] + q.w * av[r][4 * i + 3];
            }
            #pragma unroll
            for (int r = 0; r < 4; r++) lg[r][k] = acc[r] * INV_NORM;
        } else {
            #pragma unroll
            for (int r = 0; r < 4; r++) lg[r][k] = lgb[r];
        }
    }
    __syncthreads();

    // softmax over 512, 4 rows vectorized
    float v[4];
    #pragma unroll
    for (int r = 0; r < 4; r++) {
        float m = -1e30f;
        #pragma unroll
        for (int j = 0; j < 4; j++) m = fmaxf(m, lg[r][t + (j << 7)]);
        v[r] = m;
    }
    redmax4(v, red, t);
    float mx[4];
    #pragma unroll
    for (int r = 0; r < 4; r++) mx[r] = v[r];

    float ev[4][4];
    #pragma unroll
    for (int r = 0; r < 4; r++) {
        float s = 0.f;
        #pragma unroll
        for (int j = 0; j < 4; j++) {
            ev[r][j] = expf(lg[r][t + (j << 7)] - mx[r]);
            s += ev[r][j];
        }
        v[r] = s;
    }
    redsum4(v, red, t);

    #pragma unroll
    for (int r = 0; r < 4; r++) {
        int b = bq * 4 + r;
        int n = (b << 7) + p;
        int m = (p << 5) + b;
        float inv_sum = 1.0f / v[r];
        float lse = mx[r] + logf(v[r]);
        float* out_w  = out + OFF_W  + (size_t)n * KL;
        float* out_l  = out + OFF_L  + (size_t)n * KL;
        float* out_lp = out + OFF_LP + (size_t)m * KL;
        __half* wa = g_wA + (size_t)m * KP;
        #pragma unroll
        for (int j = 0; j < 4; j++) {
            int k = t + (j << 7);
            float l = lg[r][k];
            float w = ev[r][j] * inv_sum;
            out_w[k]  = w;
            out_l[k]  = l;
            out_lp[k] = l - lse;
            wa[k] = __float2half(w);
        }
    }
}

// ---------------------------------------------------------------------------
// Kernel 4: mma.sync fp16 GEMM  C[4096,16384] = A[4096,512] @ B[16384,512]^T
// CTA 128x128x32, 8 warps (4M x 2N), warp tile 32x64, double-buffered cp.async
// ---------------------------------------------------------------------------
__global__ void __launch_bounds__(256) k_gemm(float* __restrict__ outS) {
    __shared__ __align__(128) char sm[2 * STAGE_BYTES];   // [stage][A|B]

    int t = threadIdx.x;
    int lane = t & 31;
    int wid = t >> 5;
    int warp_m = wid & 3;          // 32-row slice
    int warp_n = wid >> 2;         // 64-col slice
    int n0 = blockIdx.x * TN;
    int m0 = blockIdx.y * TM;

    uint32_t smb = smem_u32(sm);

    // cp.async mapping: thread covers rows qr0 and qr0+64, 16B chunk qc
    int qr0 = t >> 2, qc = t & 3;
    int qr1 = qr0 + 64;

    const char* gA0 = (const char*)g_wA  + (size_t)(m0 + qr0) * (KP * 2);
    const char* gA1 = (const char*)g_wA  + (size_t)(m0 + qr1) * (KP * 2);
    const char* gB0 = (const char*)g_spT + (size_t)(n0 + qr0) * (KP * 2);
    const char* gB1 = (const char*)g_spT + (size_t)(n0 + qr1) * (KP * 2);

    uint32_t sA0 = smb + qr0 * RP + qc * 16;
    uint32_t sA1 = smb + qr1 * RP + qc * 16;
    uint32_t sB0 = sA0 + TILE_BYTES;
    uint32_t sB1 = sA1 + TILE_BYTES;

    uint32_t lmA = smb + (warp_m * 32 + (lane & 15)) * RP + (lane >> 4) * 16;
    uint32_t lmB = smb + TILE_BYTES
                 + (warp_n * 64 + (lane & 7) + ((lane >> 4) & 1) * 8) * RP
                 + ((lane >> 3) & 1) * 16;

    float acc[2][8][4];
    #pragma unroll
    for (int mt = 0; mt < 2; mt++)
        #pragma unroll
        for (int nt = 0; nt < 8; nt++)
            #pragma unroll
            for (int q = 0; q < 4; q++) acc[mt][nt][q] = 0.f;

    // prefetch chunk 0 -> stage 0
    CP_ASYNC16(sA0, gA0 + qc * 16);
    CP_ASYNC16(sA1, gA1 + qc * 16);
    CP_ASYNC16(sB0, gB0 + qc * 16);
    CP_ASYNC16(sB1, gB1 + qc * 16);
    CP_COMMIT();

    for (int c = 0; c < NCHUNK; c++) {
        int st = c & 1;
        if (c + 1 < NCHUNK) {
            int cb = (c + 1) * 64;            // 64 B per K-chunk
            uint32_t so = ((c + 1) & 1) * STAGE_BYTES;
            CP_ASYNC16(sA0 + so, gA0 + cb + qc * 16);
            CP_ASYNC16(sA1 + so, gA1 + cb + qc * 16);
            CP_ASYNC16(sB0 + so, gB0 + cb + qc * 16);
            CP_ASYNC16(sB1 + so, gB1 + cb + qc * 16);
            CP_COMMIT();
            CP_WAIT1();
        } else {
            CP_WAIT0();
        }
        __syncthreads();

        uint32_t aoff = lmA + st * STAGE_BYTES;
        uint32_t boff = lmB + st * STAGE_BYTES;
        #pragma unroll
        for (int kt = 0; kt < 2; kt++) {
            uint32_t a[2][4];
            #pragma unroll
            for (int mt = 0; mt < 2; mt++)
                LDSM4(a[mt][0], a[mt][1], a[mt][2], a[mt][3],
                      aoff + mt * (16 * RP) + kt * 32);
            uint32_t bfr[8][2];
            #pragma unroll
            for (int pg = 0; pg < 4; pg++)
                LDSM4(bfr[2 * pg][0], bfr[2 * pg][1],
                      bfr[2 * pg + 1][0], bfr[2 * pg + 1][1],
                      boff + pg * (16 * RP) + kt * 32);
            #pragma unroll
            for (int mt = 0; mt < 2; mt++)
                #pragma unroll
                for (int nt = 0; nt < 8; nt++)
                    mma16816(acc[mt][nt], a[mt], bfr[nt]);
        }
        __syncthreads();
    }

    // epilogue
    int rbase = m0 + warp_m * 32 + (lane >> 2);
    int cbase = n0 + warp_n * 64 + (lane & 3) * 2;
    #pragma unroll
    for (int mt = 0; mt < 2; mt++) {
        #pragma unroll
        for (int nt = 0; nt < 8; nt++) {
            int r = rbase + mt * 16;
            int cc = cbase + nt * 8;
            *(float2*)(outS + (size_t)r * Ntot + cc) =
                make_float2(acc[mt][nt][0], acc[mt][nt][1]);
            *(float2*)(outS + (size_t)(r + 8) * Ntot + cc) =
                make_float2(acc[mt][nt][2], acc[mt][nt][3]);
        }
    }
}

// ---------------------------------------------------------------------------
// Launch
// ---------------------------------------------------------------------------
extern "C" void kernel_launch(void* const* d_in, const int* in_sizes, int n_in,
                              void* d_out, int out_size) {
    const float* x       = (const float*)d_in[0];
    const float* latents = (const float*)d_in[1];
    const float* blankl  = (const float*)d_in[2];
    const float* lw      = (const float*)d_in[3];
    const float* lb      = (const float*)d_in[4];
    const float* aw      = (const float*)d_in[5];
    const float* ab      = (const float*)d_in[6];
    const float* proto   = (const float*)d_in[7];
    const float* masks   = (const float*)d_in[8];
    float* out = (float*)d_out;

    k_lat<<<(Kk + 3) / 4, 128>>>(latents, lw, lb);
    dim3 gp(Ntot / 64, KP / 64);
    k_prep<<<gp, 256>>>(proto, masks);
    k_row<<<1024, 128>>>(x, blankl, aw, ab, out);
    dim3 gg(Ntot / TN, Nn / TM);
    k_gemm<<<gg, 256>>>(out + OFF_S);
}

// round 10
// speedup vs baseline: 18.1490x; 1.3551x over previous
#include <cuda_runtime.h>
#include <cuda_fp16.h>
#include <math.h>
#include <stdint.h>

// ---------------------------------------------------------------------------
// Problem constants
// ---------------------------------------------------------------------------
#define Bb   32
#define Cc   128
#define Pp   128
#define Nn   (Bb * Pp)    // 4096 rows
#define Kk   510
#define KL   512
#define Zz   128
#define DS   256
#define HW   4096
#define EPSV 1e-5f
#define INV_NORM 0.08838834764831845f

#define KP   512
#define Ntot 16384        // 4*HW

// output layout
#define OFF_W   0
#define OFF_L   (Nn * KL)
#define OFF_LP  (2 * Nn * KL)
#define OFF_S   (3 * Nn * KL)

// GEMM tiling
#define TM 128
#define TN 128
#define TK 32                 // fp16 per k-chunk (64 B per row)
#define NCHUNK (KP / TK)      // 16
#define RP 80                 // smem row pitch (64B data + 16B pad)
#define TILE_BYTES (128 * RP) // 10240
#define STAGE_BYTES (2 * TILE_BYTES)
#define STAGES 3
#define SMEM_DYN (STAGES * STAGE_BYTES)   // 61440

// ---------------------------------------------------------------------------
// Device scratch (zero-initialized; rows k>=510 of g_spT stay zero)
// ---------------------------------------------------------------------------
__device__ __align__(16) float  g_lat[Kk * Zz];
__device__ __align__(16) __half g_wA [Nn * KP];            // 4.2 MB
__device__ __align__(16) __half g_spT[(size_t)Ntot * KP];  // 16.8 MB

// ---------------------------------------------------------------------------
// PTX helpers (sm_80-era; valid on plain compute_103 target)
// ---------------------------------------------------------------------------
__device__ __forceinline__ uint32_t smem_u32(const void* p) {
    uint32_t a;
    asm("{ .reg .u64 t; cvta.to.shared.u64 t, %1; cvt.u32.u64 %0, t; }"
        : "=r"(a) : "l"(p));
    return a;
}
#define CP_ASYNC16(dst, src) \
    asm volatile("cp.async.cg.shared.global [%0], [%1], 16;" :: "r"(dst), "l"(src))
#define CP_COMMIT() asm volatile("cp.async.commit_group;" ::: "memory")
#define CP_WAIT1()  asm volatile("cp.async.wait_group 1;" ::: "memory")

#define LDSM4(r0, r1, r2, r3, addr) \
    asm volatile("ldmatrix.sync.aligned.m8n8.x4.shared.b16 {%0,%1,%2,%3}, [%4];" \
        : "=r"(r0), "=r"(r1), "=r"(r2), "=r"(r3) : "r"(addr))

__device__ __forceinline__ void mma16816(float* c, const uint32_t* a,
                                         const uint32_t* b) {
    asm volatile(
        "mma.sync.aligned.m16n8k16.row.col.f32.f16.f16.f32 "
        "{%0,%1,%2,%3}, {%4,%5,%6,%7}, {%8,%9}, {%0,%1,%2,%3};"
        : "+f"(c[0]), "+f"(c[1]), "+f"(c[2]), "+f"(c[3])
        : "r"(a[0]), "r"(a[1]), "r"(a[2]), "r"(a[3]), "r"(b[0]), "r"(b[1]));
}

// ---------------------------------------------------------------------------
// R-row block reductions over 128 threads
// ---------------------------------------------------------------------------
template <int R>
__device__ __forceinline__ void redsumN(float v[R], float red[4][R], int t) {
    #pragma unroll
    for (int o = 16; o; o >>= 1)
        #pragma unroll
        for (int r = 0; r < R; r++) v[r] += __shfl_down_sync(0xffffffffu, v[r], o);
    if ((t & 31) == 0)
        #pragma unroll
        for (int r = 0; r < R; r++) red[t >> 5][r] = v[r];
    __syncthreads();
    #pragma unroll
    for (int r = 0; r < R; r++)
        v[r] = red[0][r] + red[1][r] + red[2][r] + red[3][r];
    __syncthreads();
}
template <int R>
__device__ __forceinline__ void redmaxN(float v[R], float red[4][R], int t) {
    #pragma unroll
    for (int o = 16; o; o >>= 1)
        #pragma unroll
        for (int r = 0; r < R; r++)
            v[r] = fmaxf(v[r], __shfl_down_sync(0xffffffffu, v[r], o));
    if ((t & 31) == 0)
        #pragma unroll
        for (int r = 0; r < R; r++) red[t >> 5][r] = v[r];
    __syncthreads();
    #pragma unroll
    for (int r = 0; r < R; r++)
        v[r] = fmaxf(fmaxf(red[0][r], red[1][r]), fmaxf(red[2][r], red[3][r]));
    __syncthreads();
}

// ---------------------------------------------------------------------------
// Kernel 1: lat = LN(latents @ linear_w^T + linear_b), 4 latents per block
// ---------------------------------------------------------------------------
__global__ void k_lat(const float* __restrict__ latents,
                      const float* __restrict__ lw,
                      const float* __restrict__ lb) {
    int k0 = blockIdx.x * 4;
    int t = threadIdx.x;
    __shared__ float lv[4][DS];
    __shared__ float red[4][4];

    #pragma unroll
    for (int r = 0; r < 4; r++) {
        int k = k0 + r;
        float a = 0.f, b2 = 0.f;
        if (k < Kk) { a = latents[k * DS + t]; b2 = latents[k * DS + t + 128]; }
        lv[r][t] = a; lv[r][t + 128] = b2;
    }
    __syncthreads();

    const float* wrow = lw + t * DS;
    float s[4] = {lb[t], lb[t], lb[t], lb[t]};
    #pragma unroll 4
    for (int d = 0; d < DS; d++) {
        float w = wrow[d];
        #pragma unroll
        for (int r = 0; r < 4; r++) s[r] += lv[r][d] * w;
    }

    float v[4];
    #pragma unroll
    for (int r = 0; r < 4; r++) v[r] = s[r];
    redsumN<4>(v, red, t);
    float d4[4];
    #pragma unroll
    for (int r = 0; r < 4; r++) {
        d4[r] = s[r] - v[r] * (1.f / 128.f);
        v[r] = d4[r] * d4[r];
    }
    redsumN<4>(v, red, t);
    #pragma unroll
    for (int r = 0; r < 4; r++) {
        int k = k0 + r;
        if (k < Kk)
            g_lat[k * Zz + t] = d4[r] * rsqrtf(v[r] * (1.f / 128.f) + EPSV);
    }
}

// ---------------------------------------------------------------------------
// Kernel 2: sprite^T fp16, [Ntot, KP] K-major (rows k>=510 remain zero)
// ---------------------------------------------------------------------------
__global__ void k_prep(const float* __restrict__ proto,
                       const float* __restrict__ masks) {
    __shared__ float tile[64][65];
    int n0 = blockIdx.x * 64;
    int k0 = blockIdx.y * 64;
    int t = threadIdx.x;

    for (int idx = t; idx < 4096; idx += 256) {
        int kk = idx >> 6, nn = idx & 63;
        int k = k0 + kk, n = n0 + nn;
        int ch = n >> 12, i = n & 4095;
        float s = 0.f;
        if (k < Kk)
            s = (ch < 3) ? proto[(size_t)k * (3 * HW) + ch * HW + i]
                         : masks[(size_t)k * HW + i];
        tile[kk][nn] = s;
    }
    __syncthreads();

    for (int idx = t; idx < 4096; idx += 256) {
        int nn = idx >> 6, kk = idx & 63;
        if (k0 + kk < Kk)
            g_spT[(size_t)(n0 + nn) * KP + k0 + kk] = __float2half(tile[kk][nn]);
    }
}

// ---------------------------------------------------------------------------
// Kernel 3: 8 rows per block (same p, 8 consecutive b)
// ---------------------------------------------------------------------------
__global__ void k_row(const float* __restrict__ x,
                      const float* __restrict__ blankl,
                      const float* __restrict__ aw,
                      const float* __restrict__ ab,
                      float* __restrict__ out) {
    int bi = blockIdx.x;          // 0..511
    int p  = bi & 127;
    int bq = bi >> 7;             // 0..3 -> b = bq*8 + r
    int t  = threadIdx.x;

    __shared__ float xv[8][Cc];
    __shared__ float av[8][Zz];
    __shared__ float lg[8][KL];
    __shared__ float red[4][8];

    #pragma unroll
    for (int r = 0; r < 8; r++)
        xv[r][t] = x[(size_t)(bq * 8 + r) * (Cc * Pp) + t * Pp + p];
    __syncthreads();

    // anchors linear + LN (8 rows)
    {
        const float* wrow = aw + t * Cc;
        float s[8];
        #pragma unroll
        for (int r = 0; r < 8; r++) s[r] = ab[t];
        #pragma unroll 4
        for (int c = 0; c < Cc; c++) {
            float w = wrow[c];
            #pragma unroll
            for (int r = 0; r < 8; r++) s[r] += xv[r][c] * w;
        }
        float v[8];
        #pragma unroll
        for (int r = 0; r < 8; r++) v[r] = s[r];
        redsumN<8>(v, red, t);
        float d8[8];
        #pragma unroll
        for (int r = 0; r < 8; r++) {
            d8[r] = s[r] - v[r] * (1.f / 128.f);
            v[r] = d8[r] * d8[r];
        }
        redsumN<8>(v, red, t);
        #pragma unroll
        for (int r = 0; r < 8; r++)
            av[r][t] = d8[r] * rsqrtf(v[r] * (1.f / 128.f) + EPSV);
    }

    // blank dots (8 rows)
    float lgb[8];
    {
        float bl = blankl[(p & 1) * Cc + t];
        float v[8];
        #pragma unroll
        for (int r = 0; r < 8; r++) v[r] = xv[r][t] * bl;
        redsumN<8>(v, red, t);
        #pragma unroll
        for (int r = 0; r < 8; r++) lgb[r] = v[r] * INV_NORM;
    }
    __syncthreads();   // av visible

    // logits: thread handles k = t + 128*j for all 8 rows
    #pragma unroll
    for (int j = 0; j < 4; j++) {
        int k = t + (j << 7);
        if (k < Kk) {
            const float4* lr = (const float4*)(g_lat + k * Zz);
            float acc[8] = {0.f, 0.f, 0.f, 0.f, 0.f, 0.f, 0.f, 0.f};
            #pragma unroll 4
            for (int i = 0; i < 32; i++) {
                float4 q = lr[i];
                #pragma unroll
                for (int r = 0; r < 8; r++)
                    acc[r] += q.x * av[r][4 * i]     + q.y * av[r][4 * i + 1]
                            + q.z * av[r][4 * i + 2] + q.w * av[r][4 * i + 3];
            }
            #pragma unroll
            for (int r = 0; r < 8; r++) lg[r][k] = acc[r] * INV_NORM;
        } else {
            #pragma unroll
            for (int r = 0; r < 8; r++) lg[r][k] = lgb[r];
        }
    }
    __syncthreads();

    // softmax over 512, 8 rows
    float v[8];
    #pragma unroll
    for (int r = 0; r < 8; r++) {
        float m = -1e30f;
        #pragma unroll
        for (int j = 0; j < 4; j++) m = fmaxf(m, lg[r][t + (j << 7)]);
        v[r] = m;
    }
    redmaxN<8>(v, red, t);
    float mx[8];
    #pragma unroll
    for (int r = 0; r < 8; r++) mx[r] = v[r];

    float ev[8][4];
    #pragma unroll
    for (int r = 0; r < 8; r++) {
        float s = 0.f;
        #pragma unroll
        for (int j = 0; j < 4; j++) {
            ev[r][j] = expf(lg[r][t + (j << 7)] - mx[r]);
            s += ev[r][j];
        }
        v[r] = s;
    }
    redsumN<8>(v, red, t);

    #pragma unroll
    for (int r = 0; r < 8; r++) {
        int b = bq * 8 + r;
        int n = (b << 7) + p;
        int m = (p << 5) + b;
        float inv_sum = 1.0f / v[r];
        float lse = mx[r] + logf(v[r]);
        float* out_w  = out + OFF_W  + (size_t)n * KL;
        float* out_l  = out + OFF_L  + (size_t)n * KL;
        float* out_lp = out + OFF_LP + (size_t)m * KL;
        __half* wa = g_wA + (size_t)m * KP;
        #pragma unroll
        for (int j = 0; j < 4; j++) {
            int k = t + (j << 7);
            float l = lg[r][k];
            float w = ev[r][j] * inv_sum;
            out_w[k]  = w;
            out_l[k]  = l;
            out_lp[k] = l - lse;
            wa[k] = __float2half(w);
        }
    }
}

// ---------------------------------------------------------------------------
// Kernel 4: mma.sync fp16 GEMM  C[4096,16384] = A[4096,512] @ B[16384,512]^T
// CTA 128x128x32, 8 warps, 3-stage cp.async pipeline, 2 CTAs/SM
// ---------------------------------------------------------------------------
__global__ void __launch_bounds__(256, 2) k_gemm(float* __restrict__ outS) {
    extern __shared__ __align__(128) char sm[];   // STAGES x [A|B]

    int t = threadIdx.x;
    int lane = t & 31;
    int wid = t >> 5;
    int warp_m = wid & 3;          // 32-row slice
    int warp_n = wid >> 2;         // 64-col slice
    int n0 = blockIdx.x * TN;
    int m0 = blockIdx.y * TM;

    uint32_t smb = smem_u32(sm);

    // cp.async mapping: thread covers rows qr0 and qr0+64, 16B chunk qc
    int qr0 = t >> 2, qc = t & 3;
    int qr1 = qr0 + 64;

    const char* gA0 = (const char*)g_wA  + (size_t)(m0 + qr0) * (KP * 2) + qc * 16;
    const char* gA1 = (const char*)g_wA  + (size_t)(m0 + qr1) * (KP * 2) + qc * 16;
    const char* gB0 = (const char*)g_spT + (size_t)(n0 + qr0) * (KP * 2) + qc * 16;
    const char* gB1 = (const char*)g_spT + (size_t)(n0 + qr1) * (KP * 2) + qc * 16;

    uint32_t sA0 = smb + qr0 * RP + qc * 16;
    uint32_t sA1 = smb + qr1 * RP + qc * 16;
    uint32_t sB0 = sA0 + TILE_BYTES;
    uint32_t sB1 = sA1 + TILE_BYTES;

    uint32_t lmA = smb + (warp_m * 32 + (lane & 15)) * RP + (lane >> 4) * 16;
    uint32_t lmB = smb + TILE_BYTES
                 + (warp_n * 64 + (lane & 7) + ((lane >> 4) & 1) * 8) * RP
                 + ((lane >> 3) & 1) * 16;

    float acc[2][8][4];
    #pragma unroll
    for (int mt = 0; mt < 2; mt++)
        #pragma unroll
        for (int nt = 0; nt < 8; nt++)
            #pragma unroll
            for (int q = 0; q < 4; q++) acc[mt][nt][q] = 0.f;

    // prefetch chunks 0,1 into stages 0,1
    #pragma unroll
    for (int s = 0; s < STAGES - 1; s++) {
        uint32_t so = s * STAGE_BYTES;
        int cb = s * 64;
        CP_ASYNC16(sA0 + so, gA0 + cb);
        CP_ASYNC16(sA1 + so, gA1 + cb);
        CP_ASYNC16(sB0 + so, gB0 + cb);
        CP_ASYNC16(sB1 + so, gB1 + cb);
        CP_COMMIT();
    }

    for (int c = 0; c < NCHUNK; c++) {
        CP_WAIT1();            // chunk c landed
        __syncthreads();       // all warps past compute of c-1 -> stage reuse safe

        // issue chunk c+2 into stage (c+2)%STAGES; always commit (group count)
        int cn = c + STAGES - 1;
        if (cn < NCHUNK) {
            uint32_t so = (cn % STAGES) * STAGE_BYTES;
            int cb = cn * 64;
            CP_ASYNC16(sA0 + so, gA0 + cb);
            CP_ASYNC16(sA1 + so, gA1 + cb);
            CP_ASYNC16(sB0 + so, gB0 + cb);
            CP_ASYNC16(sB1 + so, gB1 + cb);
        }
        CP_COMMIT();

        uint32_t aoff = lmA + (c % STAGES) * STAGE_BYTES;
        uint32_t boff = lmB + (c % STAGES) * STAGE_BYTES;
        #pragma unroll
        for (int kt = 0; kt < 2; kt++) {
            uint32_t a[2][4];
            #pragma unroll
            for (int mt = 0; mt < 2; mt++)
                LDSM4(a[mt][0], a[mt][1], a[mt][2], a[mt][3],
                      aoff + mt * (16 * RP) + kt * 32);
            uint32_t bfr[8][2];
            #pragma unroll
            for (int pg = 0; pg < 4; pg++)
                LDSM4(bfr[2 * pg][0], bfr[2 * pg][1],
                      bfr[2 * pg + 1][0], bfr[2 * pg + 1][1],
                      boff + pg * (16 * RP) + kt * 32);
            #pragma unroll
            for (int mt = 0; mt < 2; mt++)
                #pragma unroll
                for (int nt = 0; nt < 8; nt++)
                    mma16816(acc[mt][nt], a[mt], bfr[nt]);
        }
    }

    // epilogue
    int rbase = m0 + warp_m * 32 + (lane >> 2);
    int cbase = n0 + warp_n * 64 + (lane & 3) * 2;
    #pragma unroll
    for (int mt = 0; mt < 2; mt++) {
        #pragma unroll
        for (int nt = 0; nt < 8; nt++) {
            int r = rbase + mt * 16;
            int cc = cbase + nt * 8;
            *(float2*)(outS + (size_t)r * Ntot + cc) =
                make_float2(acc[mt][nt][0], acc[mt][nt][1]);
            *(float2*)(outS + (size_t)(r + 8) * Ntot + cc) =
                make_float2(acc[mt][nt][2], acc[mt][nt][3]);
        }
    }
}

// ---------------------------------------------------------------------------
// Launch
// ---------------------------------------------------------------------------
extern "C" void kernel_launch(void* const* d_in, const int* in_sizes, int n_in,
                              void* d_out, int out_size) {
    const float* x       = (const float*)d_in[0];
    const float* latents = (const float*)d_in[1];
    const float* blankl  = (const float*)d_in[2];
    const float* lw      = (const float*)d_in[3];
    const float* lb      = (const float*)d_in[4];
    const float* aw      = (const float*)d_in[5];
    const float* ab      = (const float*)d_in[6];
    const float* proto   = (const float*)d_in[7];
    const float* masks   = (const float*)d_in[8];
    float* out = (float*)d_out;

    static int smem_set = 0;
    if (!smem_set) {
        cudaFuncSetAttribute(k_gemm, cudaFuncAttributeMaxDynamicSharedMemorySize,
                             SMEM_DYN);
        smem_set = 1;
    }

    k_lat<<<(Kk + 3) / 4, 128>>>(latents, lw, lb);
    dim3 gp(Ntot / 64, KP / 64);
    k_prep<<<gp, 256>>>(proto, masks);
    k_row<<<512, 128>>>(x, blankl, aw, ab, out);
    dim3 gg(Ntot / TN, Nn / TM);
    k_gemm<<<gg, 256, SMEM_DYN>>>(out + OFF_S);
}